// round 1
// baseline (speedup 1.0000x reference)
#include <cuda_runtime.h>
#include <math.h>

#define B_DIM   8
#define C_DIM   512
#define S_DIM   1024
#define N_HEADS 8
#define DH      64
#define GROUPS  32
#define CPG     16      // channels per group
#define EPS     1e-5f

// ---------------- scratch (device globals; no allocation allowed) ----------------
__device__ float g_mean[B_DIM * GROUPS];
__device__ float g_rstd[B_DIM * GROUPS];
__device__ float g_Q[B_DIM * N_HEADS * S_DIM * DH];   // [b,h,s,d]
__device__ float g_K[B_DIM * N_HEADS * S_DIM * DH];
__device__ float g_V[B_DIM * N_HEADS * S_DIM * DH];
__device__ float g_ctx[B_DIM * S_DIM * C_DIM];        // [b,s,c]

// ============================================================================
// 1) GroupNorm statistics: one block per (b, g). Channels of a group are
//    contiguous in [B,C,S] layout -> each group is a contiguous 64KB slab.
// ============================================================================
__global__ void gn_stats_kernel(const float* __restrict__ x) {
    int bg = blockIdx.x;                       // b*32 + g
    const float4* p = (const float4*)(x + (size_t)bg * CPG * S_DIM);
    const int n4 = CPG * S_DIM / 4;            // 4096 float4
    float s = 0.f, s2 = 0.f;
    for (int i = threadIdx.x; i < n4; i += 256) {
        float4 v = p[i];
        s  += v.x + v.y + v.z + v.w;
        s2 += v.x * v.x + v.y * v.y + v.z * v.z + v.w * v.w;
    }
    __shared__ float ss[256], sq[256];
    ss[threadIdx.x] = s; sq[threadIdx.x] = s2;
    __syncthreads();
    for (int o = 128; o > 0; o >>= 1) {
        if (threadIdx.x < o) { ss[threadIdx.x] += ss[threadIdx.x + o]; sq[threadIdx.x] += sq[threadIdx.x + o]; }
        __syncthreads();
    }
    if (threadIdx.x == 0) {
        const float invN = 1.f / (CPG * S_DIM);
        float mean = ss[0] * invN;
        float var  = sq[0] * invN - mean * mean;
        g_mean[bg] = mean;
        g_rstd[bg] = rsqrtf(var + EPS);
    }
}

// ============================================================================
// 2) QKV projection GEMM. out[co, s] = sum_c W[co,c] * X[c,s] per batch.
//    X is x[b,c,s] directly (s contiguous -> coalesced). For Q the GroupNorm
//    is fused into the X-tile load. Result stored as [b, h, s, d] (d contig)
//    via an smem transpose so global stores are coalesced.
//    Grid: (S/64, C/64, B*3). Block 256 threads, 64x64 tile, 4x4 per thread.
// ============================================================================
__global__ void qkv_gemm_kernel(const float* __restrict__ x,
                                const float* __restrict__ Wq,
                                const float* __restrict__ Wk,
                                const float* __restrict__ Wv,
                                const float* __restrict__ gn_w,
                                const float* __restrict__ gn_b) {
    const int z   = blockIdx.z;
    const int mat = z % 3;            // 0=Q (normed), 1=K, 2=V
    const int b   = z / 3;
    const float* W = (mat == 0) ? Wq : (mat == 1) ? Wk : Wv;
    float* dst     = (mat == 0) ? g_Q : (mat == 1) ? g_K : g_V;

    const int s0  = blockIdx.x * 64;
    const int co0 = blockIdx.y * 64;

    __shared__ float As[16][68];      // As[kk][co_local]   (transposed W tile)
    __shared__ float Bs[16][68];      // Bs[kk][s_local]
    __shared__ float Cs[64][65];      // staging for transposed store

    const int tid = threadIdx.x;
    const int ty = tid >> 4, tx = tid & 15;

    float acc[4][4] = {};
    const float* xb = x + (size_t)b * C_DIM * S_DIM;

    for (int k0 = 0; k0 < C_DIM; k0 += 16) {
        // A tile: W[co0+row, k0+kk] -> As[kk][row]
        #pragma unroll
        for (int i = tid; i < 1024; i += 256) {
            int row = i >> 4, kk = i & 15;
            As[kk][row] = W[(size_t)(co0 + row) * C_DIM + k0 + kk];
        }
        // B tile: x[b, k0+kk, s0+col] (optionally GroupNormed)
        if (mat == 0) {
            #pragma unroll
            for (int i = tid; i < 1024; i += 256) {
                int kk = i >> 6, col = i & 63;
                int c = k0 + kk;
                float v = xb[(size_t)c * S_DIM + s0 + col];
                int gi = b * GROUPS + (c >> 4);
                v = (v - g_mean[gi]) * g_rstd[gi] * gn_w[c] + gn_b[c];
                Bs[kk][col] = v;
            }
        } else {
            #pragma unroll
            for (int i = tid; i < 1024; i += 256) {
                int kk = i >> 6, col = i & 63;
                Bs[kk][col] = xb[(size_t)(k0 + kk) * S_DIM + s0 + col];
            }
        }
        __syncthreads();
        #pragma unroll
        for (int kk = 0; kk < 16; ++kk) {
            float4 a4 = *(const float4*)&As[kk][ty * 4];
            float4 b4 = *(const float4*)&Bs[kk][tx * 4];
            float av[4] = {a4.x, a4.y, a4.z, a4.w};
            float bv[4] = {b4.x, b4.y, b4.z, b4.w};
            #pragma unroll
            for (int i = 0; i < 4; ++i)
                #pragma unroll
                for (int j = 0; j < 4; ++j)
                    acc[i][j] += av[i] * bv[j];
        }
        __syncthreads();
    }

    // stage [co][s] then store transposed -> [b,h,s,d] with d contiguous
    #pragma unroll
    for (int i = 0; i < 4; ++i)
        #pragma unroll
        for (int j = 0; j < 4; ++j)
            Cs[ty * 4 + i][tx * 4 + j] = acc[i][j];
    __syncthreads();

    // co tile == one head (64 == DH), h = blockIdx.y
    float* dsth = dst + ((size_t)(b * N_HEADS + blockIdx.y) * S_DIM) * DH;
    for (int i = tid; i < 4096; i += 256) {
        int sl = i >> 6, dl = i & 63;
        dsth[(size_t)(s0 + sl) * DH + dl] = Cs[dl][sl];
    }
}

// ============================================================================
// 3) Flash attention. One block per (b,h, 64-row s chunk). Online softmax with
//    per-thread row state (replicated across the 16-lane tx group, kept
//    consistent by identical butterfly reductions).
//    Dynamic smem: Qs[64][65] Ks[64][65] Vs[64][68] Ps[64][68] = 68096 B.
// ============================================================================
extern __shared__ float smem_attn[];

__global__ void attn_kernel() {
    float* Qs = smem_attn;                  // [64][65]
    float* Ks = Qs + 64 * 65;               // [64][65]
    float* Vs = Ks + 64 * 65;               // [64][68]
    float* Ps = Vs + 64 * 68;               // [64][68]

    const int bh = blockIdx.y;
    const int s0 = blockIdx.x * 64;
    const int tid = threadIdx.x;
    const int ty = tid >> 4, tx = tid & 15;

    const float* Qg = g_Q + (size_t)bh * S_DIM * DH;
    const float* Kg = g_K + (size_t)bh * S_DIM * DH;
    const float* Vg = g_V + (size_t)bh * S_DIM * DH;

    // Q chunk, pre-scaled by 1/sqrt(d)
    for (int i = tid; i < 4096; i += 256) {
        int r = i >> 6, d = i & 63;
        Qs[r * 65 + d] = Qg[(size_t)(s0 + r) * DH + d] * 0.125f;
    }

    float m_i[4], l_i[4], acc[4][4] = {};
    #pragma unroll
    for (int i = 0; i < 4; ++i) { m_i[i] = -1e30f; l_i[i] = 0.f; }

    for (int t0 = 0; t0 < S_DIM; t0 += 64) {
        __syncthreads();   // prev PV done (and Qs visible on first iter)
        for (int i = tid; i < 4096; i += 256) {
            int r = i >> 6, d = i & 63;
            Ks[r * 65 + d] = Kg[(size_t)(t0 + r) * DH + d];
        }
        for (int i = tid; i < 4096; i += 256) {
            int r = i >> 6, d = i & 63;
            Vs[r * 68 + d] = Vg[(size_t)(t0 + r) * DH + d];
        }
        __syncthreads();

        // S = Q K^T  (4x4 per thread)
        float s_ij[4][4] = {};
        #pragma unroll 8
        for (int kd = 0; kd < 64; ++kd) {
            float av[4], bv[4];
            #pragma unroll
            for (int i = 0; i < 4; ++i) av[i] = Qs[(ty * 4 + i) * 65 + kd];
            #pragma unroll
            for (int j = 0; j < 4; ++j) bv[j] = Ks[(tx * 4 + j) * 65 + kd];
            #pragma unroll
            for (int i = 0; i < 4; ++i)
                #pragma unroll
                for (int j = 0; j < 4; ++j)
                    s_ij[i][j] += av[i] * bv[j];
        }

        // online softmax per owned row; write P tile
        #pragma unroll
        for (int i = 0; i < 4; ++i) {
            float mx = fmaxf(fmaxf(s_ij[i][0], s_ij[i][1]), fmaxf(s_ij[i][2], s_ij[i][3]));
            #pragma unroll
            for (int off = 8; off >= 1; off >>= 1)
                mx = fmaxf(mx, __shfl_xor_sync(0xffffffffu, mx, off));
            float m_new = fmaxf(m_i[i], mx);
            float corr  = __expf(m_i[i] - m_new);
            float p0 = __expf(s_ij[i][0] - m_new);
            float p1 = __expf(s_ij[i][1] - m_new);
            float p2 = __expf(s_ij[i][2] - m_new);
            float p3 = __expf(s_ij[i][3] - m_new);
            float rs = p0 + p1 + p2 + p3;
            #pragma unroll
            for (int off = 8; off >= 1; off >>= 1)
                rs += __shfl_xor_sync(0xffffffffu, rs, off);
            l_i[i] = l_i[i] * corr + rs;
            m_i[i] = m_new;
            #pragma unroll
            for (int j = 0; j < 4; ++j) acc[i][j] *= corr;
            *(float4*)&Ps[(ty * 4 + i) * 68 + tx * 4] = make_float4(p0, p1, p2, p3);
        }
        __syncthreads();

        // acc += P @ V
        #pragma unroll 4
        for (int tt = 0; tt < 64; ++tt) {
            float4 v4 = *(const float4*)&Vs[tt * 68 + tx * 4];
            #pragma unroll
            for (int i = 0; i < 4; ++i) {
                float p = Ps[(ty * 4 + i) * 68 + tt];
                acc[i][0] += p * v4.x;
                acc[i][1] += p * v4.y;
                acc[i][2] += p * v4.z;
                acc[i][3] += p * v4.w;
            }
        }
    }

    // epilogue: normalize, stage in Ps, coalesced store to ctx [b,s,c]
    __syncthreads();
    #pragma unroll
    for (int i = 0; i < 4; ++i) {
        float inv = 1.f / l_i[i];
        *(float4*)&Ps[(ty * 4 + i) * 68 + tx * 4] =
            make_float4(acc[i][0] * inv, acc[i][1] * inv, acc[i][2] * inv, acc[i][3] * inv);
    }
    __syncthreads();

    const int b = bh >> 3, h = bh & 7;
    float* cb = g_ctx + (size_t)b * S_DIM * C_DIM + h * DH;
    for (int i = tid; i < 4096; i += 256) {
        int r = i >> 6, d = i & 63;
        cb[(size_t)(s0 + r) * C_DIM + d] = Ps[r * 68 + d];
    }
}

// ============================================================================
// 4) Output projection: out[b,co,s] = sum_c Wo[co,c]*ctx[b,s,c] + bo[co].
//    Writes directly into d_out in [B,C,H,W] layout (s contiguous) with
//    float4 stores. Grid (S/64, C/64, B).
// ============================================================================
__global__ void out_gemm_kernel(const float* __restrict__ Wo,
                                const float* __restrict__ bo,
                                float* __restrict__ out) {
    const int b = blockIdx.z;
    const int s0  = blockIdx.x * 64;
    const int co0 = blockIdx.y * 64;

    __shared__ float As[16][68];   // As[kk][co_local]
    __shared__ float Bs[16][68];   // Bs[kk][s_local]

    const int tid = threadIdx.x;
    const int ty = tid >> 4, tx = tid & 15;

    float acc[4][4] = {};
    const float* cb = g_ctx + (size_t)b * S_DIM * C_DIM;

    for (int k0 = 0; k0 < C_DIM; k0 += 16) {
        #pragma unroll
        for (int i = tid; i < 1024; i += 256) {
            int row = i >> 4, kk = i & 15;
            As[kk][row] = Wo[(size_t)(co0 + row) * C_DIM + k0 + kk];
        }
        // ctx^T tile: kk runs along contiguous c for best-effort coalescing
        #pragma unroll
        for (int i = tid; i < 1024; i += 256) {
            int kk = i & 15, col = i >> 4;
            Bs[kk][col] = cb[(size_t)(s0 + col) * C_DIM + k0 + kk];
        }
        __syncthreads();
        #pragma unroll
        for (int kk = 0; kk < 16; ++kk) {
            float4 a4 = *(const float4*)&As[kk][ty * 4];
            float4 b4 = *(const float4*)&Bs[kk][tx * 4];
            float av[4] = {a4.x, a4.y, a4.z, a4.w};
            float bv[4] = {b4.x, b4.y, b4.z, b4.w};
            #pragma unroll
            for (int i = 0; i < 4; ++i)
                #pragma unroll
                for (int j = 0; j < 4; ++j)
                    acc[i][j] += av[i] * bv[j];
        }
        __syncthreads();
    }

    float* ob = out + ((size_t)b * C_DIM + co0) * S_DIM;
    #pragma unroll
    for (int i = 0; i < 4; ++i) {
        float bias = bo[co0 + ty * 4 + i];
        float4 r = make_float4(acc[i][0] + bias, acc[i][1] + bias,
                               acc[i][2] + bias, acc[i][3] + bias);
        *(float4*)&ob[(size_t)(ty * 4 + i) * S_DIM + s0 + tx * 4] = r;
    }
}

// ============================================================================
extern "C" void kernel_launch(void* const* d_in, const int* in_sizes, int n_in,
                              void* d_out, int out_size) {
    const float* x    = (const float*)d_in[0];
    const float* gn_w = (const float*)d_in[1];
    const float* gn_b = (const float*)d_in[2];
    const float* Wq   = (const float*)d_in[3];
    const float* Wk   = (const float*)d_in[4];
    const float* Wv   = (const float*)d_in[5];
    const float* Wo   = (const float*)d_in[6];
    const float* bo   = (const float*)d_in[7];
    float* out = (float*)d_out;

    gn_stats_kernel<<<B_DIM * GROUPS, 256>>>(x);

    qkv_gemm_kernel<<<dim3(S_DIM / 64, C_DIM / 64, B_DIM * 3), 256>>>(
        x, Wq, Wk, Wv, gn_w, gn_b);

    const int attn_smem = (64 * 65 * 2 + 64 * 68 * 2) * (int)sizeof(float); // 68096 B
    cudaFuncSetAttribute(attn_kernel, cudaFuncAttributeMaxDynamicSharedMemorySize, attn_smem);
    attn_kernel<<<dim3(S_DIM / 64, B_DIM * N_HEADS), 256, attn_smem>>>();

    out_gemm_kernel<<<dim3(S_DIM / 64, C_DIM / 64, B_DIM), 256>>>(Wo, bo, out);
}

// round 3
// speedup vs baseline: 1.5862x; 1.5862x over previous
#include <cuda_runtime.h>
#include <cstdint>
#include <math.h>

#define B_DIM   8
#define C_DIM   512
#define S_DIM   1024
#define N_HEADS 8
#define DH      64
#define GROUPS  32
#define CPG     16
#define EPS     1e-5f

#define ASTRIDE 36          // smem stage stride (floats) per row of 32 k
#define DSTRIDE 133         // smem D-staging stride

// ---------------- device scratch (no allocation allowed) ----------------
__device__ float g_mean[B_DIM * GROUPS];
__device__ float g_rstd[B_DIM * GROUPS];
__device__ float g_xT [(size_t)B_DIM * S_DIM * C_DIM];   // [b,s,c] raw
__device__ float g_xnT[(size_t)B_DIM * S_DIM * C_DIM];   // [b,s,c] group-normed
__device__ float g_Q[(size_t)B_DIM * N_HEADS * S_DIM * DH];
__device__ float g_K[(size_t)B_DIM * N_HEADS * S_DIM * DH];
__device__ float g_V[(size_t)B_DIM * N_HEADS * S_DIM * DH];
__device__ float g_ctx[(size_t)B_DIM * S_DIM * C_DIM];   // [b,s,c]

// ---------------- helpers ----------------
__device__ __forceinline__ uint32_t f2tf32(float f) {
    uint32_t r;
    asm("cvt.rna.tf32.f32 %0, %1;" : "=r"(r) : "f"(f));
    return r;
}

__device__ __forceinline__ void mma_tf32(float c[4], const uint32_t a[4], const uint32_t b[2]) {
    asm volatile(
        "mma.sync.aligned.m16n8k8.row.col.f32.tf32.tf32.f32 "
        "{%0,%1,%2,%3},{%4,%5,%6,%7},{%8,%9},{%0,%1,%2,%3};"
        : "+f"(c[0]), "+f"(c[1]), "+f"(c[2]), "+f"(c[3])
        : "r"(a[0]), "r"(a[1]), "r"(a[2]), "r"(a[3]), "r"(b[0]), "r"(b[1]));
}

// ============================================================================
// 1) GroupNorm statistics
// ============================================================================
__global__ void gn_stats_kernel(const float* __restrict__ x) {
    int bg = blockIdx.x;
    const float4* p = (const float4*)(x + (size_t)bg * CPG * S_DIM);
    const int n4 = CPG * S_DIM / 4;
    float s = 0.f, s2 = 0.f;
    for (int i = threadIdx.x; i < n4; i += 256) {
        float4 v = p[i];
        s  += v.x + v.y + v.z + v.w;
        s2 += v.x * v.x + v.y * v.y + v.z * v.z + v.w * v.w;
    }
    __shared__ float ss[256], sq[256];
    ss[threadIdx.x] = s; sq[threadIdx.x] = s2;
    __syncthreads();
    for (int o = 128; o > 0; o >>= 1) {
        if (threadIdx.x < o) { ss[threadIdx.x] += ss[threadIdx.x + o]; sq[threadIdx.x] += sq[threadIdx.x + o]; }
        __syncthreads();
    }
    if (threadIdx.x == 0) {
        const float invN = 1.f / (CPG * S_DIM);
        float mean = ss[0] * invN;
        float var  = sq[0] * invN - mean * mean;
        g_mean[bg] = mean;
        g_rstd[bg] = rsqrtf(var + EPS);
    }
}

// ============================================================================
// 2) x transpose [b,c,s] -> [b,s,c], raw + GroupNormed (fp32)
// ============================================================================
__global__ void prep_x_kernel(const float* __restrict__ x,
                              const float* __restrict__ gw, const float* __restrict__ gb) {
    __shared__ float t[32][33];
    int b = blockIdx.z, s0 = blockIdx.x * 32, c0 = blockIdx.y * 32;
    const float* xb = x + ((size_t)b * C_DIM + c0) * S_DIM + s0;
    #pragma unroll
    for (int j = 0; j < 4; ++j) {
        int c = threadIdx.y + j * 8;
        t[c][threadIdx.x] = xb[(size_t)c * S_DIM + threadIdx.x];
    }
    __syncthreads();
    int c = c0 + threadIdx.x;
    float w = gw[c], bia = gb[c];
    int gi = b * GROUPS + (c >> 4);
    float mu = g_mean[gi], rs = g_rstd[gi];
    #pragma unroll
    for (int j = 0; j < 4; ++j) {
        int s = s0 + threadIdx.y + j * 8;
        float v = t[threadIdx.x][threadIdx.y + j * 8];
        size_t o = ((size_t)b * S_DIM + s) * C_DIM + c;
        g_xT[o]  = v;
        g_xnT[o] = (v - mu) * rs * w + bia;
    }
}

// ============================================================================
// tf32 mma.sync GEMM core: D[128,128] = A[128,512] * B[128,512]^T
// (both operands K-major with ld = 512). 8 warps, warp tile 64x32.
// Smem stage: [128][ASTRIDE] per operand, double buffered, k-permuted so
// A frags = 2x LDS.64 and B frags = 1x LDS.64.
// ============================================================================
struct GemmOut { float acc[4][4][4]; };   // [m16 i][n8 j][reg]

__device__ __forceinline__ void gemm_mainloop(
    const float* __restrict__ Ag,   // [128][512] row-major slice
    const float* __restrict__ Bg,   // [128][512] row-major slice
    uint32_t* As, uint32_t* Bs,     // smem [2][128*ASTRIDE] each
    float acc[4][4][4])
{
    const int tid  = threadIdx.x;
    const int lane = tid & 31;
    const int warp = tid >> 5;
    const int my = warp >> 2;       // 0..1  (M 64-row half)
    const int wx = warp & 3;        // 0..3  (N 32-col quarter)
    const int tg = lane & 3, gp = lane >> 2;

    // per-thread loader coordinates: idx = it*256+tid; row=idx>>3; cq=idx&7
    float4 pa[4], pb[4];

#define LDG_STAGE(k0_) do { \
    _Pragma("unroll") \
    for (int it = 0; it < 4; ++it) { \
        int idx = it * 256 + tid; \
        int row = idx >> 3, cq = idx & 7; \
        pa[it] = *(const float4*)(Ag + (size_t)row * C_DIM + (k0_) + cq * 4); \
        pb[it] = *(const float4*)(Bg + (size_t)row * C_DIM + (k0_) + cq * 4); \
    } \
} while (0)

#define STS_STAGE(buf_) do { \
    uint32_t* Ad = As + (buf_) * (128 * ASTRIDE); \
    uint32_t* Bd = Bs + (buf_) * (128 * ASTRIDE); \
    _Pragma("unroll") \
    for (int it = 0; it < 4; ++it) { \
        int idx = it * 256 + tid; \
        int row = idx >> 3, cq = idx & 7; \
        int base = row * ASTRIDE + (cq >> 1) * 8 + (cq & 1); \
        float av[4] = {pa[it].x, pa[it].y, pa[it].z, pa[it].w}; \
        float bv[4] = {pb[it].x, pb[it].y, pb[it].z, pb[it].w}; \
        _Pragma("unroll") \
        for (int j = 0; j < 4; ++j) { \
            Ad[base + 2 * j] = f2tf32(av[j]); \
            Bd[base + 2 * j] = f2tf32(bv[j]); \
        } \
    } \
} while (0)

    LDG_STAGE(0);
    STS_STAGE(0);
    LDG_STAGE(32);
    __syncthreads();

    const int NSTAGE = C_DIM / 32;   // 16
    for (int s = 0; s < NSTAGE; ++s) {
        const uint32_t* Ab = As + (s & 1) * (128 * ASTRIDE);
        const uint32_t* Bb = Bs + (s & 1) * (128 * ASTRIDE);
        #pragma unroll
        for (int k8 = 0; k8 < 4; ++k8) {
            uint32_t af[4][4];
            #pragma unroll
            for (int mi = 0; mi < 4; ++mi) {
                int row = my * 64 + mi * 16 + gp;
                uint2 lo = *(const uint2*)&Ab[row * ASTRIDE + k8 * 8 + tg * 2];
                uint2 hi = *(const uint2*)&Ab[(row + 8) * ASTRIDE + k8 * 8 + tg * 2];
                af[mi][0] = lo.x; af[mi][1] = hi.x; af[mi][2] = lo.y; af[mi][3] = hi.y;
            }
            uint32_t bf[4][2];
            #pragma unroll
            for (int nj = 0; nj < 4; ++nj) {
                int col = wx * 32 + nj * 8 + gp;
                uint2 bb = *(const uint2*)&Bb[col * ASTRIDE + k8 * 8 + tg * 2];
                bf[nj][0] = bb.x; bf[nj][1] = bb.y;
            }
            #pragma unroll
            for (int mi = 0; mi < 4; ++mi)
                #pragma unroll
                for (int nj = 0; nj < 4; ++nj)
                    mma_tf32(acc[mi][nj], af[mi], bf[nj]);
        }
        if (s + 1 < NSTAGE) STS_STAGE((s + 1) & 1);
        if (s + 2 < NSTAGE) LDG_STAGE((s + 2) * 32);
        __syncthreads();
    }
#undef LDG_STAGE
#undef STS_STAGE
}

// stage accumulators into smem D tile [128][DSTRIDE]
__device__ __forceinline__ void stage_D(float* Ds, const float acc[4][4][4]) {
    const int lane = threadIdx.x & 31;
    const int warp = threadIdx.x >> 5;
    const int my = warp >> 2, wx = warp & 3;
    const int tg = lane & 3, gp = lane >> 2;
    #pragma unroll
    for (int mi = 0; mi < 4; ++mi) {
        int r = my * 64 + mi * 16 + gp;
        #pragma unroll
        for (int nj = 0; nj < 4; ++nj) {
            int c = wx * 32 + nj * 8 + tg * 2;
            Ds[r * DSTRIDE + c]           = acc[mi][nj][0];
            Ds[r * DSTRIDE + c + 1]       = acc[mi][nj][1];
            Ds[(r + 8) * DSTRIDE + c]     = acc[mi][nj][2];
            Ds[(r + 8) * DSTRIDE + c + 1] = acc[mi][nj][3];
        }
    }
}

// ============================================================================
// 3) QKV projection: D[co=128, s=128] = W[co,:] . xT/xnT[s,:]
//    -> stores fp32 [b,h,s,d]
// ============================================================================
__global__ void __launch_bounds__(256) qkv_mma_kernel(const float* __restrict__ Wq,
                                                      const float* __restrict__ Wk,
                                                      const float* __restrict__ Wv) {
    extern __shared__ uint32_t sm[];
    uint32_t* As = sm;
    uint32_t* Bs = sm + 2 * 128 * ASTRIDE;

    int z = blockIdx.z;
    int mat = z % 3, b = z / 3;
    int co0 = blockIdx.y * 128, s0 = blockIdx.x * 128;

    const float* W  = (mat == 0) ? Wq : (mat == 1) ? Wk : Wv;
    const float* Bt = ((mat == 0) ? g_xnT : g_xT) + (size_t)b * S_DIM * C_DIM;
    const float* Ag = W + (size_t)co0 * C_DIM;
    const float* Bg = Bt + (size_t)s0 * C_DIM;

    float acc[4][4][4] = {};
    gemm_mainloop(Ag, Bg, As, Bs, acc);

    float* Ds = (float*)sm;     // reuse (final mainloop sync already done)
    stage_D(Ds, acc);
    __syncthreads();

    float* dst = (mat == 0) ? g_Q : (mat == 1) ? g_K : g_V;
    int tid = threadIdx.x;
    #pragma unroll
    for (int it = 0; it < 16; ++it) {
        int i = it * 256 + tid;
        int d0  = (i & 15) * 4;
        int s_l = (i >> 4) & 127;
        int h_l = i >> 11;            // 0..1
        int row = h_l * 64 + d0;
        float4 v = make_float4(Ds[row * DSTRIDE + s_l],
                               Ds[(row + 1) * DSTRIDE + s_l],
                               Ds[(row + 2) * DSTRIDE + s_l],
                               Ds[(row + 3) * DSTRIDE + s_l]);
        int h = (co0 >> 6) + h_l;
        int s = s0 + s_l;
        *(float4*)&dst[(((size_t)(b * N_HEADS + h)) * S_DIM + s) * DH + d0] = v;
    }
}

// ============================================================================
// 4) SIMT flash attention (R1-proven), fp32, writes g_ctx [b,s,c]
// ============================================================================
extern __shared__ float smem_attn[];

__global__ void attn_kernel() {
    float* Qs = smem_attn;
    float* Ks = Qs + 64 * 65;
    float* Vs = Ks + 64 * 65;
    float* Ps = Vs + 64 * 68;

    const int bh = blockIdx.y;
    const int s0 = blockIdx.x * 64;
    const int tid = threadIdx.x;
    const int ty = tid >> 4, tx = tid & 15;

    const float* Qg = g_Q + (size_t)bh * S_DIM * DH;
    const float* Kg = g_K + (size_t)bh * S_DIM * DH;
    const float* Vg = g_V + (size_t)bh * S_DIM * DH;

    for (int i = tid; i < 4096; i += 256) {
        int r = i >> 6, d = i & 63;
        Qs[r * 65 + d] = Qg[(size_t)(s0 + r) * DH + d] * 0.125f;
    }

    float m_i[4], l_i[4], acc[4][4] = {};
    #pragma unroll
    for (int i = 0; i < 4; ++i) { m_i[i] = -1e30f; l_i[i] = 0.f; }

    for (int t0 = 0; t0 < S_DIM; t0 += 64) {
        __syncthreads();
        for (int i = tid; i < 4096; i += 256) {
            int r = i >> 6, d = i & 63;
            Ks[r * 65 + d] = Kg[(size_t)(t0 + r) * DH + d];
        }
        for (int i = tid; i < 4096; i += 256) {
            int r = i >> 6, d = i & 63;
            Vs[r * 68 + d] = Vg[(size_t)(t0 + r) * DH + d];
        }
        __syncthreads();

        float s_ij[4][4] = {};
        #pragma unroll 8
        for (int kd = 0; kd < 64; ++kd) {
            float av[4], bv[4];
            #pragma unroll
            for (int i = 0; i < 4; ++i) av[i] = Qs[(ty * 4 + i) * 65 + kd];
            #pragma unroll
            for (int j = 0; j < 4; ++j) bv[j] = Ks[(tx * 4 + j) * 65 + kd];
            #pragma unroll
            for (int i = 0; i < 4; ++i)
                #pragma unroll
                for (int j = 0; j < 4; ++j)
                    s_ij[i][j] += av[i] * bv[j];
        }

        #pragma unroll
        for (int i = 0; i < 4; ++i) {
            float mx = fmaxf(fmaxf(s_ij[i][0], s_ij[i][1]), fmaxf(s_ij[i][2], s_ij[i][3]));
            #pragma unroll
            for (int off = 8; off >= 1; off >>= 1)
                mx = fmaxf(mx, __shfl_xor_sync(0xffffffffu, mx, off));
            float m_new = fmaxf(m_i[i], mx);
            float corr  = __expf(m_i[i] - m_new);
            float p0 = __expf(s_ij[i][0] - m_new);
            float p1 = __expf(s_ij[i][1] - m_new);
            float p2 = __expf(s_ij[i][2] - m_new);
            float p3 = __expf(s_ij[i][3] - m_new);
            float rs = p0 + p1 + p2 + p3;
            #pragma unroll
            for (int off = 8; off >= 1; off >>= 1)
                rs += __shfl_xor_sync(0xffffffffu, rs, off);
            l_i[i] = l_i[i] * corr + rs;
            m_i[i] = m_new;
            #pragma unroll
            for (int j = 0; j < 4; ++j) acc[i][j] *= corr;
            *(float4*)&Ps[(ty * 4 + i) * 68 + tx * 4] = make_float4(p0, p1, p2, p3);
        }
        __syncthreads();

        #pragma unroll 4
        for (int tt = 0; tt < 64; ++tt) {
            float4 v4 = *(const float4*)&Vs[tt * 68 + tx * 4];
            #pragma unroll
            for (int i = 0; i < 4; ++i) {
                float p = Ps[(ty * 4 + i) * 68 + tt];
                acc[i][0] += p * v4.x;
                acc[i][1] += p * v4.y;
                acc[i][2] += p * v4.z;
                acc[i][3] += p * v4.w;
            }
        }
    }

    __syncthreads();
    #pragma unroll
    for (int i = 0; i < 4; ++i) {
        float inv = 1.f / l_i[i];
        *(float4*)&Ps[(ty * 4 + i) * 68 + tx * 4] =
            make_float4(acc[i][0] * inv, acc[i][1] * inv, acc[i][2] * inv, acc[i][3] * inv);
    }
    __syncthreads();

    const int b = bh >> 3, h = bh & 7;
    float* cb = g_ctx + (size_t)b * S_DIM * C_DIM + h * DH;
    for (int i = tid; i < 4096; i += 256) {
        int r = i >> 6, d = i & 63;
        cb[(size_t)(s0 + r) * C_DIM + d] = Ps[r * 68 + d];
    }
}

// ============================================================================
// 5) Output projection: D[co=128, s=128] = Wo[co,:] . ctx[s,:] + bo
//    writes straight into d_out [B,C,H,W] (s contiguous)
// ============================================================================
__global__ void __launch_bounds__(256) out_mma_kernel(const float* __restrict__ Wo,
                                                      const float* __restrict__ bo,
                                                      float* __restrict__ out) {
    extern __shared__ uint32_t sm[];
    uint32_t* As = sm;
    uint32_t* Bs = sm + 2 * 128 * ASTRIDE;

    int b = blockIdx.z;
    int co0 = blockIdx.y * 128, s0 = blockIdx.x * 128;

    const float* Ag = Wo + (size_t)co0 * C_DIM;
    const float* Bg = g_ctx + ((size_t)b * S_DIM + s0) * C_DIM;

    float acc[4][4][4] = {};
    gemm_mainloop(Ag, Bg, As, Bs, acc);

    float* Ds = (float*)sm;
    stage_D(Ds, acc);
    __syncthreads();

    int tid = threadIdx.x;
    #pragma unroll
    for (int it = 0; it < 16; ++it) {
        int i = it * 256 + tid;
        int s4   = (i & 31) * 4;
        int co_l = i >> 5;
        float bias = bo[co0 + co_l];
        float4 v = make_float4(Ds[co_l * DSTRIDE + s4]     + bias,
                               Ds[co_l * DSTRIDE + s4 + 1] + bias,
                               Ds[co_l * DSTRIDE + s4 + 2] + bias,
                               Ds[co_l * DSTRIDE + s4 + 3] + bias);
        *(float4*)&out[((size_t)b * C_DIM + co0 + co_l) * S_DIM + s0 + s4] = v;
    }
}

// ============================================================================
extern "C" void kernel_launch(void* const* d_in, const int* in_sizes, int n_in,
                              void* d_out, int out_size) {
    const float* x    = (const float*)d_in[0];
    const float* gn_w = (const float*)d_in[1];
    const float* gn_b = (const float*)d_in[2];
    const float* Wq   = (const float*)d_in[3];
    const float* Wk   = (const float*)d_in[4];
    const float* Wv   = (const float*)d_in[5];
    const float* Wo   = (const float*)d_in[6];
    const float* bo   = (const float*)d_in[7];
    float* out = (float*)d_out;

    const int gemm_smem = 4 * 128 * ASTRIDE * (int)sizeof(float);   // 73728 B

    gn_stats_kernel<<<B_DIM * GROUPS, 256>>>(x);
    prep_x_kernel<<<dim3(S_DIM / 32, C_DIM / 32, B_DIM), dim3(32, 8)>>>(x, gn_w, gn_b);

    cudaFuncSetAttribute(qkv_mma_kernel, cudaFuncAttributeMaxDynamicSharedMemorySize, gemm_smem);
    qkv_mma_kernel<<<dim3(S_DIM / 128, C_DIM / 128, B_DIM * 3), 256, gemm_smem>>>(Wq, Wk, Wv);

    const int attn_smem = (64 * 65 * 2 + 64 * 68 * 2) * (int)sizeof(float);
    cudaFuncSetAttribute(attn_kernel, cudaFuncAttributeMaxDynamicSharedMemorySize, attn_smem);
    attn_kernel<<<dim3(S_DIM / 64, B_DIM * N_HEADS), 256, attn_smem>>>();

    cudaFuncSetAttribute(out_mma_kernel, cudaFuncAttributeMaxDynamicSharedMemorySize, gemm_smem);
    out_mma_kernel<<<dim3(S_DIM / 128, C_DIM / 128, B_DIM), 256, gemm_smem>>>(Wo, bo, out);
}

// round 5
// speedup vs baseline: 2.7266x; 1.7189x over previous
#include <cuda_runtime.h>
#include <cstdint>
#include <math.h>

#define B_DIM   8
#define C_DIM   512
#define S_DIM   1024
#define N_HEADS 8
#define DH      64
#define GROUPS  32
#define CPG     16
#define EPS     1e-5f

#define ASTRIDE 36          // gemm smem stage stride (floats) per 32-k row
#define DSTRIDE 133         // gemm smem D-staging stride
#define QK_STRIDE 68        // attn Q/K smem row stride (2 chunks of 34)
#define PV_STRIDE 136       // attn P/V smem row stride (4 chunks of 34)

// ---------------- device scratch (no allocation allowed) ----------------
__device__ float g_mean[B_DIM * GROUPS];
__device__ float g_rstd[B_DIM * GROUPS];
__device__ float g_xT [(size_t)B_DIM * S_DIM * C_DIM];   // [b,s,c] raw
__device__ float g_xnT[(size_t)B_DIM * S_DIM * C_DIM];   // [b,s,c] group-normed
__device__ float g_Q[(size_t)B_DIM * N_HEADS * S_DIM * DH];   // [b,h,s,d]
__device__ float g_K[(size_t)B_DIM * N_HEADS * S_DIM * DH];   // [b,h,s,d]
__device__ float g_V[(size_t)B_DIM * N_HEADS * DH * S_DIM];   // [b,h,d,s]  (transposed!)
__device__ float g_ctx[(size_t)B_DIM * S_DIM * C_DIM];   // [b,s,c]

// ---------------- helpers ----------------
__device__ __forceinline__ uint32_t f2tf32(float f) {
    uint32_t r;
    asm("cvt.rna.tf32.f32 %0, %1;" : "=r"(r) : "f"(f));
    return r;
}

__device__ __forceinline__ void mma_tf32(float c[4], const uint32_t a[4], const uint32_t b[2]) {
    asm volatile(
        "mma.sync.aligned.m16n8k8.row.col.f32.tf32.tf32.f32 "
        "{%0,%1,%2,%3},{%4,%5,%6,%7},{%8,%9},{%0,%1,%2,%3};"
        : "+f"(c[0]), "+f"(c[1]), "+f"(c[2]), "+f"(c[3])
        : "r"(a[0]), "r"(a[1]), "r"(a[2]), "r"(a[3]), "r"(b[0]), "r"(b[1]));
}

// ============================================================================
// 1) GroupNorm statistics
// ============================================================================
__global__ void gn_stats_kernel(const float* __restrict__ x) {
    int bg = blockIdx.x;
    const float4* p = (const float4*)(x + (size_t)bg * CPG * S_DIM);
    const int n4 = CPG * S_DIM / 4;
    float s = 0.f, s2 = 0.f;
    for (int i = threadIdx.x; i < n4; i += 256) {
        float4 v = p[i];
        s  += v.x + v.y + v.z + v.w;
        s2 += v.x * v.x + v.y * v.y + v.z * v.z + v.w * v.w;
    }
    __shared__ float ss[256], sq[256];
    ss[threadIdx.x] = s; sq[threadIdx.x] = s2;
    __syncthreads();
    for (int o = 128; o > 0; o >>= 1) {
        if (threadIdx.x < o) { ss[threadIdx.x] += ss[threadIdx.x + o]; sq[threadIdx.x] += sq[threadIdx.x + o]; }
        __syncthreads();
    }
    if (threadIdx.x == 0) {
        const float invN = 1.f / (CPG * S_DIM);
        float mean = ss[0] * invN;
        float var  = sq[0] * invN - mean * mean;
        g_mean[bg] = mean;
        g_rstd[bg] = rsqrtf(var + EPS);
    }
}

// ============================================================================
// 2) x transpose [b,c,s] -> [b,s,c], raw + GroupNormed (fp32)
// ============================================================================
__global__ void prep_x_kernel(const float* __restrict__ x,
                              const float* __restrict__ gw, const float* __restrict__ gb) {
    __shared__ float t[32][33];
    int b = blockIdx.z, s0 = blockIdx.x * 32, c0 = blockIdx.y * 32;
    const float* xb = x + ((size_t)b * C_DIM + c0) * S_DIM + s0;
    #pragma unroll
    for (int j = 0; j < 4; ++j) {
        int c = threadIdx.y + j * 8;
        t[c][threadIdx.x] = xb[(size_t)c * S_DIM + threadIdx.x];
    }
    __syncthreads();
    int c = c0 + threadIdx.x;
    float w = gw[c], bia = gb[c];
    int gi = b * GROUPS + (c >> 4);
    float mu = g_mean[gi], rs = g_rstd[gi];
    #pragma unroll
    for (int j = 0; j < 4; ++j) {
        int s = s0 + threadIdx.y + j * 8;
        float v = t[threadIdx.x][threadIdx.y + j * 8];
        size_t o = ((size_t)b * S_DIM + s) * C_DIM + c;
        g_xT[o]  = v;
        g_xnT[o] = (v - mu) * rs * w + bia;
    }
}

// ============================================================================
// tf32 mma.sync GEMM core (proven R3): D[128,128] = A[128,512]*B[128,512]^T
// ============================================================================
__device__ __forceinline__ void gemm_mainloop(
    const float* __restrict__ Ag, const float* __restrict__ Bg,
    uint32_t* As, uint32_t* Bs, float acc[4][4][4])
{
    const int tid  = threadIdx.x;
    const int lane = tid & 31;
    const int warp = tid >> 5;
    const int my = warp >> 2, wx = warp & 3;
    const int tg = lane & 3, gp = lane >> 2;
    float4 pa[4], pb[4];

#define LDG_STAGE(k0_) do { \
    _Pragma("unroll") \
    for (int it = 0; it < 4; ++it) { \
        int idx = it * 256 + tid; \
        int row = idx >> 3, cq = idx & 7; \
        pa[it] = *(const float4*)(Ag + (size_t)row * C_DIM + (k0_) + cq * 4); \
        pb[it] = *(const float4*)(Bg + (size_t)row * C_DIM + (k0_) + cq * 4); \
    } \
} while (0)

#define STS_STAGE(buf_) do { \
    uint32_t* Ad = As + (buf_) * (128 * ASTRIDE); \
    uint32_t* Bd = Bs + (buf_) * (128 * ASTRIDE); \
    _Pragma("unroll") \
    for (int it = 0; it < 4; ++it) { \
        int idx = it * 256 + tid; \
        int row = idx >> 3, cq = idx & 7; \
        int base = row * ASTRIDE + (cq >> 1) * 8 + (cq & 1); \
        float av[4] = {pa[it].x, pa[it].y, pa[it].z, pa[it].w}; \
        float bv[4] = {pb[it].x, pb[it].y, pb[it].z, pb[it].w}; \
        _Pragma("unroll") \
        for (int j = 0; j < 4; ++j) { \
            Ad[base + 2 * j] = f2tf32(av[j]); \
            Bd[base + 2 * j] = f2tf32(bv[j]); \
        } \
    } \
} while (0)

    LDG_STAGE(0);
    STS_STAGE(0);
    LDG_STAGE(32);
    __syncthreads();

    const int NSTAGE = C_DIM / 32;
    for (int s = 0; s < NSTAGE; ++s) {
        const uint32_t* Ab = As + (s & 1) * (128 * ASTRIDE);
        const uint32_t* Bb = Bs + (s & 1) * (128 * ASTRIDE);
        #pragma unroll
        for (int k8 = 0; k8 < 4; ++k8) {
            uint32_t af[4][4];
            #pragma unroll
            for (int mi = 0; mi < 4; ++mi) {
                int row = my * 64 + mi * 16 + gp;
                uint2 lo = *(const uint2*)&Ab[row * ASTRIDE + k8 * 8 + tg * 2];
                uint2 hi = *(const uint2*)&Ab[(row + 8) * ASTRIDE + k8 * 8 + tg * 2];
                af[mi][0] = lo.x; af[mi][1] = hi.x; af[mi][2] = lo.y; af[mi][3] = hi.y;
            }
            uint32_t bf[4][2];
            #pragma unroll
            for (int nj = 0; nj < 4; ++nj) {
                int col = wx * 32 + nj * 8 + gp;
                uint2 bb = *(const uint2*)&Bb[col * ASTRIDE + k8 * 8 + tg * 2];
                bf[nj][0] = bb.x; bf[nj][1] = bb.y;
            }
            #pragma unroll
            for (int mi = 0; mi < 4; ++mi)
                #pragma unroll
                for (int nj = 0; nj < 4; ++nj)
                    mma_tf32(acc[mi][nj], af[mi], bf[nj]);
        }
        if (s + 1 < NSTAGE) STS_STAGE((s + 1) & 1);
        if (s + 2 < NSTAGE) LDG_STAGE((s + 2) * 32);
        __syncthreads();
    }
#undef LDG_STAGE
#undef STS_STAGE
}

__device__ __forceinline__ void stage_D(float* Ds, const float acc[4][4][4]) {
    const int lane = threadIdx.x & 31;
    const int warp = threadIdx.x >> 5;
    const int my = warp >> 2, wx = warp & 3;
    const int tg = lane & 3, gp = lane >> 2;
    #pragma unroll
    for (int mi = 0; mi < 4; ++mi) {
        int r = my * 64 + mi * 16 + gp;
        #pragma unroll
        for (int nj = 0; nj < 4; ++nj) {
            int c = wx * 32 + nj * 8 + tg * 2;
            Ds[r * DSTRIDE + c]           = acc[mi][nj][0];
            Ds[r * DSTRIDE + c + 1]       = acc[mi][nj][1];
            Ds[(r + 8) * DSTRIDE + c]     = acc[mi][nj][2];
            Ds[(r + 8) * DSTRIDE + c + 1] = acc[mi][nj][3];
        }
    }
}

// ============================================================================
// 3) QKV projection. Q,K stored [b,h,s,d]; V stored transposed [b,h,d,s].
// ============================================================================
__global__ void __launch_bounds__(256) qkv_mma_kernel(const float* __restrict__ Wq,
                                                      const float* __restrict__ Wk,
                                                      const float* __restrict__ Wv) {
    extern __shared__ uint32_t sm[];
    uint32_t* As = sm;
    uint32_t* Bs = sm + 2 * 128 * ASTRIDE;

    int z = blockIdx.z;
    int mat = z % 3, b = z / 3;
    int co0 = blockIdx.y * 128, s0 = blockIdx.x * 128;

    const float* W  = (mat == 0) ? Wq : (mat == 1) ? Wk : Wv;
    const float* Bt = ((mat == 0) ? g_xnT : g_xT) + (size_t)b * S_DIM * C_DIM;
    const float* Ag = W + (size_t)co0 * C_DIM;
    const float* Bg = Bt + (size_t)s0 * C_DIM;

    float acc[4][4][4] = {};
    gemm_mainloop(Ag, Bg, As, Bs, acc);

    float* Ds = (float*)sm;
    stage_D(Ds, acc);
    __syncthreads();

    int tid = threadIdx.x;
    if (mat == 2) {
        // Vt[b,h,d,s]: rows co_l = (h_l, d), cols = s  (coalesced along s)
        #pragma unroll
        for (int it = 0; it < 16; ++it) {
            int i = it * 256 + tid;
            int s4 = (i & 31) * 4, co_l = i >> 5;
            int h = (co0 >> 6) + (co_l >> 6), d = co_l & 63;
            float4 v = make_float4(Ds[co_l * DSTRIDE + s4],     Ds[co_l * DSTRIDE + s4 + 1],
                                   Ds[co_l * DSTRIDE + s4 + 2], Ds[co_l * DSTRIDE + s4 + 3]);
            *(float4*)&g_V[(((size_t)(b * N_HEADS + h)) * DH + d) * S_DIM + s0 + s4] = v;
        }
    } else {
        float* dst = (mat == 0) ? g_Q : g_K;
        #pragma unroll
        for (int it = 0; it < 16; ++it) {
            int i = it * 256 + tid;
            int d0  = (i & 15) * 4;
            int s_l = (i >> 4) & 127;
            int h_l = i >> 11;
            int row = h_l * 64 + d0;
            float4 v = make_float4(Ds[row * DSTRIDE + s_l],
                                   Ds[(row + 1) * DSTRIDE + s_l],
                                   Ds[(row + 2) * DSTRIDE + s_l],
                                   Ds[(row + 3) * DSTRIDE + s_l]);
            int h = (co0 >> 6) + h_l;
            int s = s0 + s_l;
            *(float4*)&dst[(((size_t)(b * N_HEADS + h)) * S_DIM + s) * DH + d0] = v;
        }
    }
}

// ============================================================================
// 4) Tensor-core flash attention. 256 thr, q-tile 128, kv-tile 128.
//    S-mma warp tile 64x32 (K=64); PV-mma warp tile 64x16 (K=128).
//    All smem chunk strides EVEN (34) so uint2 accesses stay 8B-aligned.
// ============================================================================
__global__ void __launch_bounds__(256, 1) attn_mma_kernel() {
    extern __shared__ float sm_f[];
    uint32_t* Qs = (uint32_t*)sm_f;              // 128 * QK_STRIDE
    uint32_t* Ks = Qs + 128 * QK_STRIDE;         // 128 * QK_STRIDE
    uint32_t* Vs = Ks + 128 * QK_STRIDE;         // 64  * PV_STRIDE
    float*    Ps = (float*)(Vs + 64 * PV_STRIDE);// 128 * PV_STRIDE (S raw -> P tf32)
    float*    corr_s = Ps + 128 * PV_STRIDE;     // 128
    float*    lrow   = corr_s + 128;             // 128

    const int tid = threadIdx.x;
    const int lane = tid & 31, warp = tid >> 5;
    const int tg = lane & 3, gp = lane >> 2;
    const int mw = warp >> 2;     // q 64-half (both mmas)
    const int wx = warp & 3;      // S: kv 32-quarter; PV: d 16-quarter
    const int bh = blockIdx.y;
    const int b = bh >> 3, h = bh & 7;
    const int s0 = blockIdx.x * 128;

    const float* Qg  = g_Q + (size_t)bh * S_DIM * DH;
    const float* Kg  = g_K + (size_t)bh * S_DIM * DH;
    const float* Vtg = g_V + (size_t)bh * DH * S_DIM;   // [d][s]

    // Q tile: tf32, k-permuted, pre-scaled
    #pragma unroll
    for (int it = 0; it < 8; ++it) {
        int idx = it * 256 + tid;
        int row = idx >> 4, f4 = idx & 15;
        float4 v = *(const float4*)(Qg + (size_t)(s0 + row) * DH + f4 * 4);
        int chunk = f4 >> 3, cq = f4 & 7;
        uint32_t* p = Qs + row * QK_STRIDE + chunk * 34 + ((cq >> 1) << 3) + (cq & 1);
        p[0] = f2tf32(v.x * 0.125f); p[2] = f2tf32(v.y * 0.125f);
        p[4] = f2tf32(v.z * 0.125f); p[6] = f2tf32(v.w * 0.125f);
    }

    float m_i = -1e30f, l_i = 0.f;
    float o_acc[4][2][4] = {};
    const int r_sm = tid >> 1, hf = tid & 1;     // softmax role: 2 threads/row

    for (int t0 = 0; t0 < S_DIM; t0 += 128) {
        __syncthreads();     // prev PV done; (iter0: Qs visible)
        // K tile [kv=128][d=64]
        #pragma unroll
        for (int it = 0; it < 8; ++it) {
            int idx = it * 256 + tid;
            int row = idx >> 4, f4 = idx & 15;
            float4 v = *(const float4*)(Kg + (size_t)(t0 + row) * DH + f4 * 4);
            int chunk = f4 >> 3, cq = f4 & 7;
            uint32_t* p = Ks + row * QK_STRIDE + chunk * 34 + ((cq >> 1) << 3) + (cq & 1);
            p[0] = f2tf32(v.x); p[2] = f2tf32(v.y); p[4] = f2tf32(v.z); p[6] = f2tf32(v.w);
        }
        // V tile (Vt rows d=64, kv cols contiguous)
        #pragma unroll
        for (int it = 0; it < 8; ++it) {
            int idx = it * 256 + tid;
            int d = idx >> 5, f4 = idx & 31;
            float4 v = *(const float4*)(Vtg + (size_t)d * S_DIM + t0 + f4 * 4);
            int chunk = f4 >> 3, cq = f4 & 7;
            uint32_t* p = Vs + d * PV_STRIDE + chunk * 34 + ((cq >> 1) << 3) + (cq & 1);
            p[0] = f2tf32(v.x); p[2] = f2tf32(v.y); p[4] = f2tf32(v.z); p[6] = f2tf32(v.w);
        }
        __syncthreads();

        // ---- S = Q K^T ----
        float s_acc[4][4][4] = {};
        #pragma unroll
        for (int k8 = 0; k8 < 8; ++k8) {
            int koff = (k8 >> 2) * 34 + (k8 & 3) * 8 + tg * 2;
            uint32_t af[4][4];
            #pragma unroll
            for (int mi = 0; mi < 4; ++mi) {
                int row = mw * 64 + mi * 16 + gp;
                uint2 lo = *(const uint2*)&Qs[row * QK_STRIDE + koff];
                uint2 hi = *(const uint2*)&Qs[(row + 8) * QK_STRIDE + koff];
                af[mi][0] = lo.x; af[mi][1] = hi.x; af[mi][2] = lo.y; af[mi][3] = hi.y;
            }
            #pragma unroll
            for (int nj = 0; nj < 4; ++nj) {
                int col = wx * 32 + nj * 8 + gp;
                uint2 bb = *(const uint2*)&Ks[col * QK_STRIDE + koff];
                uint32_t bf[2] = {bb.x, bb.y};
                #pragma unroll
                for (int mi = 0; mi < 4; ++mi)
                    mma_tf32(s_acc[mi][nj], af[mi], bf);
            }
        }
        // store S tile to Ps (linear within 34-slot chunks)
        #pragma unroll
        for (int mi = 0; mi < 4; ++mi) {
            int r = mw * 64 + mi * 16 + gp;
            #pragma unroll
            for (int nj = 0; nj < 4; ++nj) {
                float* p0 = Ps + r * PV_STRIDE + wx * 34 + nj * 8 + tg * 2;
                p0[0] = s_acc[mi][nj][0];
                p0[1] = s_acc[mi][nj][1];
                p0[8 * PV_STRIDE]     = s_acc[mi][nj][2];
                p0[8 * PV_STRIDE + 1] = s_acc[mi][nj][3];
            }
        }
        __syncthreads();

        // ---- online softmax: row r_sm, cols hf*64..+63 ----
        {
            float vals[64];
            float* base = Ps + r_sm * PV_STRIDE + (2 * hf) * 34;
            #pragma unroll
            for (int j = 0; j < 32; ++j) vals[j]      = base[j];
            #pragma unroll
            for (int j = 0; j < 32; ++j) vals[32 + j] = base[34 + j];
            float mx = vals[0];
            #pragma unroll
            for (int j = 1; j < 64; ++j) mx = fmaxf(mx, vals[j]);
            mx = fmaxf(mx, __shfl_xor_sync(0xffffffffu, mx, 1));
            float m_new = fmaxf(m_i, mx);
            float c = __expf(m_i - m_new);
            float sum = 0.f;
            #pragma unroll
            for (int j = 0; j < 64; ++j) { vals[j] = __expf(vals[j] - m_new); sum += vals[j]; }
            sum += __shfl_xor_sync(0xffffffffu, sum, 1);
            l_i = l_i * c + sum;
            m_i = m_new;
            uint32_t* ub = (uint32_t*)base;
            #pragma unroll
            for (int j = 0; j < 32; ++j) {
                int cq = j >> 2, jj = j & 3;
                ub[((cq >> 1) << 3) + (cq & 1) + 2 * jj] = f2tf32(vals[j]);
            }
            #pragma unroll
            for (int j = 0; j < 32; ++j) {
                int cq = j >> 2, jj = j & 3;
                ub[34 + ((cq >> 1) << 3) + (cq & 1) + 2 * jj] = f2tf32(vals[32 + j]);
            }
            if (hf == 0) { corr_s[r_sm] = c; lrow[r_sm] = l_i; }
        }
        __syncthreads();

        // ---- rescale O, then O += P V ----
        #pragma unroll
        for (int mi = 0; mi < 4; ++mi) {
            int r = mw * 64 + mi * 16 + gp;
            float c0 = corr_s[r], c1 = corr_s[r + 8];
            #pragma unroll
            for (int nj = 0; nj < 2; ++nj) {
                o_acc[mi][nj][0] *= c0; o_acc[mi][nj][1] *= c0;
                o_acc[mi][nj][2] *= c1; o_acc[mi][nj][3] *= c1;
            }
        }
        const uint32_t* Pu = (const uint32_t*)Ps;
        #pragma unroll
        for (int k8 = 0; k8 < 16; ++k8) {
            int koff = (k8 >> 2) * 34 + (k8 & 3) * 8 + tg * 2;
            uint32_t af[4][4];
            #pragma unroll
            for (int mi = 0; mi < 4; ++mi) {
                int row = mw * 64 + mi * 16 + gp;
                uint2 lo = *(const uint2*)&Pu[row * PV_STRIDE + koff];
                uint2 hi = *(const uint2*)&Pu[(row + 8) * PV_STRIDE + koff];
                af[mi][0] = lo.x; af[mi][1] = hi.x; af[mi][2] = lo.y; af[mi][3] = hi.y;
            }
            #pragma unroll
            for (int nj = 0; nj < 2; ++nj) {
                int col = wx * 16 + nj * 8 + gp;
                uint2 bb = *(const uint2*)&Vs[col * PV_STRIDE + koff];
                uint32_t bf[2] = {bb.x, bb.y};
                #pragma unroll
                for (int mi = 0; mi < 4; ++mi)
                    mma_tf32(o_acc[mi][nj], af[mi], bf);
            }
        }
    }

    // ---- epilogue: normalize, stage, coalesced ctx store ----
    __syncthreads();                 // last PV's Ps reads done
    float* Ds = Ps;                  // reuse, stride 68
    #pragma unroll
    for (int mi = 0; mi < 4; ++mi) {
        int r = mw * 64 + mi * 16 + gp;
        float inv0 = 1.f / lrow[r], inv1 = 1.f / lrow[r + 8];
        #pragma unroll
        for (int nj = 0; nj < 2; ++nj) {
            int c = wx * 16 + nj * 8 + tg * 2;
            Ds[r * 68 + c]           = o_acc[mi][nj][0] * inv0;
            Ds[r * 68 + c + 1]       = o_acc[mi][nj][1] * inv0;
            Ds[(r + 8) * 68 + c]     = o_acc[mi][nj][2] * inv1;
            Ds[(r + 8) * 68 + c + 1] = o_acc[mi][nj][3] * inv1;
        }
    }
    __syncthreads();
    float* cb = g_ctx + ((size_t)b * S_DIM + s0) * C_DIM + h * DH;
    #pragma unroll
    for (int it = 0; it < 8; ++it) {
        int idx = it * 256 + tid;
        int r = idx >> 4, c4 = (idx & 15) * 4;
        float4 v = make_float4(Ds[r * 68 + c4],     Ds[r * 68 + c4 + 1],
                               Ds[r * 68 + c4 + 2], Ds[r * 68 + c4 + 3]);
        *(float4*)(cb + (size_t)r * C_DIM + c4) = v;
    }
}

// ============================================================================
// 5) Output projection (unchanged from R3)
// ============================================================================
__global__ void __launch_bounds__(256) out_mma_kernel(const float* __restrict__ Wo,
                                                      const float* __restrict__ bo,
                                                      float* __restrict__ out) {
    extern __shared__ uint32_t sm[];
    uint32_t* As = sm;
    uint32_t* Bs = sm + 2 * 128 * ASTRIDE;

    int b = blockIdx.z;
    int co0 = blockIdx.y * 128, s0 = blockIdx.x * 128;

    const float* Ag = Wo + (size_t)co0 * C_DIM;
    const float* Bg = g_ctx + ((size_t)b * S_DIM + s0) * C_DIM;

    float acc[4][4][4] = {};
    gemm_mainloop(Ag, Bg, As, Bs, acc);

    float* Ds = (float*)sm;
    stage_D(Ds, acc);
    __syncthreads();

    int tid = threadIdx.x;
    #pragma unroll
    for (int it = 0; it < 16; ++it) {
        int i = it * 256 + tid;
        int s4   = (i & 31) * 4;
        int co_l = i >> 5;
        float bias = bo[co0 + co_l];
        float4 v = make_float4(Ds[co_l * DSTRIDE + s4]     + bias,
                               Ds[co_l * DSTRIDE + s4 + 1] + bias,
                               Ds[co_l * DSTRIDE + s4 + 2] + bias,
                               Ds[co_l * DSTRIDE + s4 + 3] + bias);
        *(float4*)&out[((size_t)b * C_DIM + co0 + co_l) * S_DIM + s0 + s4] = v;
    }
}

// ============================================================================
extern "C" void kernel_launch(void* const* d_in, const int* in_sizes, int n_in,
                              void* d_out, int out_size) {
    const float* x    = (const float*)d_in[0];
    const float* gn_w = (const float*)d_in[1];
    const float* gn_b = (const float*)d_in[2];
    const float* Wq   = (const float*)d_in[3];
    const float* Wk   = (const float*)d_in[4];
    const float* Wv   = (const float*)d_in[5];
    const float* Wo   = (const float*)d_in[6];
    const float* bo   = (const float*)d_in[7];
    float* out = (float*)d_out;

    const int gemm_smem = 4 * 128 * ASTRIDE * (int)sizeof(float);   // 73728 B
    const int attn_smem = (128 * QK_STRIDE * 2 + 64 * PV_STRIDE +
                           128 * PV_STRIDE + 256) * (int)sizeof(float);  // 175104 B

    gn_stats_kernel<<<B_DIM * GROUPS, 256>>>(x);
    prep_x_kernel<<<dim3(S_DIM / 32, C_DIM / 32, B_DIM), dim3(32, 8)>>>(x, gn_w, gn_b);

    cudaFuncSetAttribute(qkv_mma_kernel, cudaFuncAttributeMaxDynamicSharedMemorySize, gemm_smem);
    qkv_mma_kernel<<<dim3(S_DIM / 128, C_DIM / 128, B_DIM * 3), 256, gemm_smem>>>(Wq, Wk, Wv);

    cudaFuncSetAttribute(attn_mma_kernel, cudaFuncAttributeMaxDynamicSharedMemorySize, attn_smem);
    attn_mma_kernel<<<dim3(S_DIM / 128, B_DIM * N_HEADS), 256, attn_smem>>>();

    cudaFuncSetAttribute(out_mma_kernel, cudaFuncAttributeMaxDynamicSharedMemorySize, gemm_smem);
    out_mma_kernel<<<dim3(S_DIM / 128, C_DIM / 128, B_DIM), 256, gemm_smem>>>(Wo, bo, out);
}